// round 1
// baseline (speedup 1.0000x reference)
#include <cuda_runtime.h>
#include <math.h>

#define BB 16
#define S_PAST 4096
#define S_TOT 4097
#define DD 1024
#define HH 16
#define HDI 64
#define SP 4104      // padded per-(b,h) score stride
#define CHUNK 128
#define NCH 33       // ceil(4097/128)

// ---------------- scratch (static device globals; no allocation) ----------------
__device__ float g_q[BB * DD];                       // projected, scaled query
__device__ float g_qkt[BB * HH * DD];                // folded q @ Wk per head
__device__ float g_qbk[BB * HH];                     // q_h . bk_h
__device__ float g_attn[BB * HH * SP];               // scores -> normalized attn
__device__ float g_partial[(size_t)BB * NCH * HH * DD]; // per-chunk weighted value sums
__device__ float g_wsum[BB * HH * DD];               // reduced weighted value sums
__device__ float g_ctx[BB * DD];                     // attention context

// ---------------------------------------------------------------------------
// K1a: q[b,o] = (query[b,:] . w_in[o,:] + b_in[o]) * hd^-0.5
// grid (8, B), block 256. warp-cooperative dot per output.
__global__ void __launch_bounds__(256) k_qproj(const float* __restrict__ query,
                                               const float* __restrict__ w_in,
                                               const float* __restrict__ b_in) {
    int b = blockIdx.y;
    int obase = blockIdx.x * 128;
    int t = threadIdx.x, w = t >> 5, l = t & 31;
    __shared__ float q[DD];
    ((float4*)q)[t] = ((const float4*)(query + (size_t)b * DD))[t];
    __syncthreads();
    const float4* q4 = (const float4*)q;
    for (int k = 0; k < 16; k++) {
        int o = obase + w * 16 + k;
        const float4* wr = (const float4*)(w_in + (size_t)o * DD);
        float a = 0.f;
#pragma unroll
        for (int i = 0; i < 8; i++) {
            float4 x = q4[l + 32 * i], y = wr[l + 32 * i];
            a += x.x * y.x + x.y * y.y + x.z * y.z + x.w * y.w;
        }
#pragma unroll
        for (int off = 16; off; off >>= 1) a += __shfl_xor_sync(~0u, a, off);
        if (l == 0) g_q[b * DD + o] = (a + b_in[o]) * 0.125f;  // 64^-0.5
    }
}

// ---------------------------------------------------------------------------
// K1b: qkt[b,h,d] = sum_{j<64} q[b,64h+j] * w_in[D+64h+j, d]   (axpy form, coalesced)
//      qbk[b,h]   = sum_{j<64} q[b,64h+j] * b_in[D+64h+j]
// grid (H, B), block 256 (one float4 column per thread).
__global__ void __launch_bounds__(256) k_qkt(const float* __restrict__ w_in,
                                             const float* __restrict__ b_in) {
    int b = blockIdx.y, h = blockIdx.x;
    int t = threadIdx.x;
    __shared__ float qh[HDI];
    if (t < HDI) qh[t] = g_q[b * DD + h * HDI + t];
    __syncthreads();
    if (t == 0) {
        float s = 0.f;
        for (int j = 0; j < HDI; j++) s += qh[j] * b_in[DD + h * HDI + j];
        g_qbk[b * HH + h] = s;
    }
    float4 acc = make_float4(0.f, 0.f, 0.f, 0.f);
    const float4* wk4 = (const float4*)(w_in + (size_t)(DD + h * HDI) * DD);
#pragma unroll 4
    for (int j = 0; j < HDI; j++) {
        float qv = qh[j];
        float4 wv = wk4[(size_t)j * 256 + t];
        acc.x += qv * wv.x; acc.y += qv * wv.y; acc.z += qv * wv.z; acc.w += qv * wv.w;
    }
    ((float4*)g_qkt)[(size_t)(b * HH + h) * 256 + t] = acc;
}

// ---------------------------------------------------------------------------
__device__ __forceinline__ const float4* row_src(const float* __restrict__ past,
                                                 const float* __restrict__ cur,
                                                 int b, int s) {
    return (s < S_PAST) ? (const float4*)(past + ((size_t)b * S_PAST + s) * DD)
                        : (const float4*)(cur + (size_t)b * DD);
}

// K2: streaming scores + comb_key write-through.
// grid (NCH, B), block 256 (8 warps, 2 heads/warp, qkt register-resident).
__global__ void __launch_bounds__(256) k_scores(const float* __restrict__ past_key,
                                                const float* __restrict__ key,
                                                float* __restrict__ comb_key) {
    int chunk = blockIdx.x, b = blockIdx.y;
    int t = threadIdx.x, w = t >> 5, l = t & 31;
    int s0 = chunk * CHUNK;
    int nrows = min(CHUNK, S_TOT - s0);

    __shared__ float4 buf[2][256];

    int h0 = 2 * w, h1 = 2 * w + 1;
    float4 qr0[8], qr1[8];
    const float4* qk0 = (const float4*)(g_qkt + (size_t)(b * HH + h0) * DD);
    const float4* qk1 = (const float4*)(g_qkt + (size_t)(b * HH + h1) * DD);
#pragma unroll
    for (int i = 0; i < 8; i++) { qr0[i] = qk0[l + 32 * i]; qr1[i] = qk1[l + 32 * i]; }
    float qb0 = g_qbk[b * HH + h0], qb1 = g_qbk[b * HH + h1];

    float4* ck4 = (float4*)comb_key;

    // preload row 0 (load + write-through)
    {
        float4 v = row_src(past_key, key, b, s0)[t];
        buf[0][t] = v;
        ck4[((size_t)b * S_TOT + s0) * 256 + t] = v;
    }
    for (int r = 0; r < nrows; r++) {
        __syncthreads();
        if (r + 1 < nrows) {
            float4 v = row_src(past_key, key, b, s0 + r + 1)[t];
            buf[(r + 1) & 1][t] = v;
            ck4[((size_t)b * S_TOT + s0 + r + 1) * 256 + t] = v;
        }
        const float4* rb = buf[r & 1];
        float a0 = 0.f, a1 = 0.f;
#pragma unroll
        for (int i = 0; i < 8; i++) {
            float4 rr = rb[l + 32 * i];
            a0 += qr0[i].x * rr.x + qr0[i].y * rr.y + qr0[i].z * rr.z + qr0[i].w * rr.w;
            a1 += qr1[i].x * rr.x + qr1[i].y * rr.y + qr1[i].z * rr.z + qr1[i].w * rr.w;
        }
#pragma unroll
        for (int off = 16; off; off >>= 1) {
            a0 += __shfl_xor_sync(~0u, a0, off);
            a1 += __shfl_xor_sync(~0u, a1, off);
        }
        if (l == 0) g_attn[(size_t)(b * HH + h0) * SP + s0 + r] = a0 + qb0;
        if (l == 1) g_attn[(size_t)(b * HH + h1) * SP + s0 + r] = a1 + qb1;
    }
}

// ---------------------------------------------------------------------------
// K3: per-(b,h) softmax over 4097 scores, normalized in place.
__global__ void __launch_bounds__(256) k_softmax() {
    int bh = blockIdx.x;
    int t = threadIdx.x;
    float* sc = g_attn + (size_t)bh * SP;
    float vals[17];
    int cnt = 0;
    float m = -1e30f;
    for (int i = t; i < S_TOT; i += 256) { float x = sc[i]; vals[cnt++] = x; m = fmaxf(m, x); }
    __shared__ float red[256];
    red[t] = m; __syncthreads();
    for (int off = 128; off; off >>= 1) { if (t < off) red[t] = fmaxf(red[t], red[t + off]); __syncthreads(); }
    m = red[0]; __syncthreads();
    float sum = 0.f;
    for (int j = 0; j < cnt; j++) { vals[j] = expf(vals[j] - m); sum += vals[j]; }
    red[t] = sum; __syncthreads();
    for (int off = 128; off; off >>= 1) { if (t < off) red[t] += red[t + off]; __syncthreads(); }
    float inv = 1.f / red[0];
    cnt = 0;
    for (int i = t; i < S_TOT; i += 256) sc[i] = vals[cnt++] * inv;
}

// ---------------------------------------------------------------------------
// K4: streaming attn-weighted value sum (per-chunk partials) + comb_value write-through.
// grid (NCH, B), block 256, 16 float4 accumulators per thread.
__global__ void __launch_bounds__(256) k_vsum(const float* __restrict__ past_value,
                                              const float* __restrict__ value,
                                              float* __restrict__ comb_value) {
    int chunk = blockIdx.x, b = blockIdx.y;
    int t = threadIdx.x;
    int s0 = chunk * CHUNK, nrows = min(CHUNK, S_TOT - s0);

    __shared__ float attn_s[HH * CHUNK];
    for (int i = t; i < HH * CHUNK; i += 256) {
        int h = i / CHUNK, sl = i % CHUNK;
        attn_s[i] = (sl < nrows) ? g_attn[(size_t)(b * HH + h) * SP + s0 + sl] : 0.f;
    }
    __syncthreads();

    float4 acc[HH];
#pragma unroll
    for (int h = 0; h < HH; h++) acc[h] = make_float4(0.f, 0.f, 0.f, 0.f);

    float4* cv4 = (float4*)comb_value;
    float4 v = row_src(past_value, value, b, s0)[t];
    for (int r = 0; r < nrows; r++) {
        float4 vn = make_float4(0.f, 0.f, 0.f, 0.f);
        if (r + 1 < nrows) vn = row_src(past_value, value, b, s0 + r + 1)[t];
        cv4[((size_t)b * S_TOT + s0 + r) * 256 + t] = v;
#pragma unroll
        for (int h = 0; h < HH; h++) {
            float a = attn_s[h * CHUNK + r];
            acc[h].x += a * v.x; acc[h].y += a * v.y; acc[h].z += a * v.z; acc[h].w += a * v.w;
        }
        v = vn;
    }
    float4* part = (float4*)(g_partial + ((size_t)(b * NCH + chunk) * HH) * DD);
#pragma unroll
    for (int h = 0; h < HH; h++) part[(size_t)h * 256 + t] = acc[h];
}

// ---------------------------------------------------------------------------
// K5: reduce chunk partials -> g_wsum. grid 256, block 256 (one float4 each).
__global__ void __launch_bounds__(256) k_reduce() {
    int idx = blockIdx.x * 256 + threadIdx.x;  // over B*H*256 float4
    int b = idx >> 12;
    int rem = idx & 4095;   // h*256 + dq
    float4 acc = make_float4(0.f, 0.f, 0.f, 0.f);
    for (int c = 0; c < NCH; c++) {
        float4 p = ((const float4*)g_partial)[((size_t)(b * NCH + c) * HH) * 256 + rem];
        acc.x += p.x; acc.y += p.y; acc.z += p.z; acc.w += p.w;
    }
    ((float4*)g_wsum)[idx] = acc;
}

// ---------------------------------------------------------------------------
// K6a: ctx[b,o] = w_in[2D+o,:] . wsum[b, o/64, :] + b_in[2D+o]
__global__ void __launch_bounds__(256) k_ctx(const float* __restrict__ w_in,
                                             const float* __restrict__ b_in) {
    int b = blockIdx.y;
    int obase = blockIdx.x * 128;   // grid (8, B); covers heads 2*bx, 2*bx+1
    int t = threadIdx.x, w = t >> 5, l = t & 31;
    int h0 = obase >> 6;
    __shared__ float ws[2 * DD];
    for (int i = t; i < 512; i += 256)
        ((float4*)ws)[i] = ((const float4*)(g_wsum + (size_t)(b * HH + h0) * DD))[i];
    __syncthreads();
    for (int k = 0; k < 16; k++) {
        int o = obase + w * 16 + k;
        const float4* wr = (const float4*)(w_in + (size_t)(2 * DD + o) * DD);
        const float4* xs = (const float4*)(ws + ((o >> 6) - h0) * DD);
        float a = 0.f;
#pragma unroll
        for (int i = 0; i < 8; i++) {
            float4 x = xs[l + 32 * i], y = wr[l + 32 * i];
            a += x.x * y.x + x.y * y.y + x.z * y.z + x.w * y.w;
        }
#pragma unroll
        for (int off = 16; off; off >>= 1) a += __shfl_xor_sync(~0u, a, off);
        if (l == 0) g_ctx[b * DD + o] = a + b_in[2 * DD + o];
    }
}

// K6b: out[b,p] = w_out[p,:] . ctx[b,:] + b_out[p]
__global__ void __launch_bounds__(256) k_out(const float* __restrict__ w_out,
                                             const float* __restrict__ b_out,
                                             float* __restrict__ out) {
    int b = blockIdx.y;
    int obase = blockIdx.x * 128;
    int t = threadIdx.x, w = t >> 5, l = t & 31;
    __shared__ float cx[DD];
    ((float4*)cx)[t] = ((const float4*)(g_ctx + (size_t)b * DD))[t];
    __syncthreads();
    const float4* c4 = (const float4*)cx;
    for (int k = 0; k < 16; k++) {
        int o = obase + w * 16 + k;
        const float4* wr = (const float4*)(w_out + (size_t)o * DD);
        float a = 0.f;
#pragma unroll
        for (int i = 0; i < 8; i++) {
            float4 x = c4[l + 32 * i], y = wr[l + 32 * i];
            a += x.x * y.x + x.y * y.y + x.z * y.z + x.w * y.w;
        }
#pragma unroll
        for (int off = 16; off; off >>= 1) a += __shfl_xor_sync(~0u, a, off);
        if (l == 0) out[b * DD + o] = a + b_out[o];
    }
}

// ---------------------------------------------------------------------------
extern "C" void kernel_launch(void* const* d_in, const int* in_sizes, int n_in,
                              void* d_out, int out_size) {
    const float* query      = (const float*)d_in[0];
    const float* key        = (const float*)d_in[1];
    const float* value      = (const float*)d_in[2];
    const float* past_key   = (const float*)d_in[3];
    const float* past_value = (const float*)d_in[4];
    const float* w_in       = (const float*)d_in[5];
    const float* b_in       = (const float*)d_in[6];
    const float* w_out      = (const float*)d_in[7];
    const float* b_out      = (const float*)d_in[8];

    float* out        = (float*)d_out;
    float* comb_key   = out + (size_t)BB * DD;
    float* comb_value = comb_key + (size_t)BB * S_TOT * DD;

    k_qproj  <<<dim3(8, BB), 256>>>(query, w_in, b_in);
    k_qkt    <<<dim3(HH, BB), 256>>>(w_in, b_in);
    k_scores <<<dim3(NCH, BB), 256>>>(past_key, key, comb_key);
    k_softmax<<<BB * HH, 256>>>();
    k_vsum   <<<dim3(NCH, BB), 256>>>(past_value, value, comb_value);
    k_reduce <<<256, 256>>>();
    k_ctx    <<<dim3(8, BB), 256>>>(w_in, b_in);
    k_out    <<<dim3(8, BB), 256>>>(w_out, b_out, out);
}

// round 2
// speedup vs baseline: 1.1218x; 1.1218x over previous
#include <cuda_runtime.h>
#include <math.h>

#define BB 16
#define S_PAST 4096
#define S_TOT 4097
#define DD 1024
#define HH 16
#define HDI 64
#define SP 4104      // padded per-(b,h) score stride
#define CHUNK 128
#define NCH 33       // ceil(4097/128)
#define BATCH 8      // rows per smem stage in k_scores

// ---------------- scratch (static device globals; no allocation) ----------------
__device__ __align__(16) float g_q[BB * DD];
__device__ __align__(16) float g_qkt[BB * HH * DD];
__device__ float g_qbk[BB * HH];
__device__ __align__(16) float g_attn[BB * HH * SP];
__device__ __align__(16) float g_partial[(size_t)BB * NCH * HH * DD];
__device__ __align__(16) float g_ctx[BB * DD];

// packed fp32x2 FMA (Blackwell): d = a*b + d elementwise on packed pairs
__device__ __forceinline__ void ffma2(unsigned long long& d, unsigned long long a,
                                      unsigned long long b) {
    asm("fma.rn.f32x2 %0, %1, %2, %0;" : "+l"(d) : "l"(a), "l"(b));
}
union U64F2 { unsigned long long u; float2 f; };
__device__ __forceinline__ float hadd2(unsigned long long a) {
    U64F2 t; t.u = a; return t.f.x + t.f.y;
}

// ---------------------------------------------------------------------------
// K1a: q[b,o] = (query[b,:] . w_in[o,:] + b_in[o]) * hd^-0.5
__global__ void __launch_bounds__(256) k_qproj(const float* __restrict__ query,
                                               const float* __restrict__ w_in,
                                               const float* __restrict__ b_in) {
    int b = blockIdx.y;
    int obase = blockIdx.x * 128;
    int t = threadIdx.x, w = t >> 5, l = t & 31;
    __shared__ float q[DD];
    ((float4*)q)[t] = ((const float4*)(query + (size_t)b * DD))[t];
    __syncthreads();
    const float4* q4 = (const float4*)q;
    for (int k = 0; k < 16; k++) {
        int o = obase + w * 16 + k;
        const float4* wr = (const float4*)(w_in + (size_t)o * DD);
        float a = 0.f;
#pragma unroll
        for (int i = 0; i < 8; i++) {
            float4 x = q4[l + 32 * i], y = wr[l + 32 * i];
            a += x.x * y.x + x.y * y.y + x.z * y.z + x.w * y.w;
        }
#pragma unroll
        for (int off = 16; off; off >>= 1) a += __shfl_xor_sync(~0u, a, off);
        if (l == 0) g_q[b * DD + o] = (a + b_in[o]) * 0.125f;
    }
}

// ---------------------------------------------------------------------------
// K1b: qkt[b,h,d] = sum_j q[b,64h+j] * w_in[D+64h+j, d];  qbk[b,h] = q_h . bk_h
__global__ void __launch_bounds__(256) k_qkt(const float* __restrict__ w_in,
                                             const float* __restrict__ b_in) {
    int b = blockIdx.y, h = blockIdx.x;
    int t = threadIdx.x;
    __shared__ float qh[HDI];
    if (t < HDI) qh[t] = g_q[b * DD + h * HDI + t];
    __syncthreads();
    if (t == 0) {
        float s = 0.f;
        for (int j = 0; j < HDI; j++) s += qh[j] * b_in[DD + h * HDI + j];
        g_qbk[b * HH + h] = s;
    }
    float4 acc = make_float4(0.f, 0.f, 0.f, 0.f);
    const float4* wk4 = (const float4*)(w_in + (size_t)(DD + h * HDI) * DD);
#pragma unroll 4
    for (int j = 0; j < HDI; j++) {
        float qv = qh[j];
        float4 wv = wk4[(size_t)j * 256 + t];
        acc.x += qv * wv.x; acc.y += qv * wv.y; acc.z += qv * wv.z; acc.w += qv * wv.w;
    }
    ((float4*)g_qkt)[(size_t)(b * HH + h) * 256 + t] = acc;
}

// ---------------------------------------------------------------------------
__device__ __forceinline__ const float4* row_src(const float* __restrict__ past,
                                                 const float* __restrict__ cur,
                                                 int b, int s) {
    return (s < S_PAST) ? (const float4*)(past + ((size_t)b * S_PAST + s) * DD)
                        : (const float4*)(cur + (size_t)b * DD);
}

// ---------------------------------------------------------------------------
// K2: streaming scores + comb_key write-through.
// Batches of 8 rows double-buffered in dynamic SMEM; 2 heads/warp, qkt in regs.
__global__ void __launch_bounds__(256, 2) k_scores(const float* __restrict__ past_key,
                                                   const float* __restrict__ key,
                                                   float* __restrict__ comb_key) {
    extern __shared__ float4 buf[];  // [2][BATCH*256]
    int chunk = blockIdx.x, b = blockIdx.y;
    int t = threadIdx.x, w = t >> 5, l = t & 31;
    int s0 = chunk * CHUNK;
    int nrows = min(CHUNK, S_TOT - s0);
    int nbt = (nrows + BATCH - 1) / BATCH;

    int h0 = 2 * w, h1 = h0 + 1;
    ulonglong2 q0[8], q1[8];
    const ulonglong2* qk0 = (const ulonglong2*)(g_qkt + (size_t)(b * HH + h0) * DD);
    const ulonglong2* qk1 = (const ulonglong2*)(g_qkt + (size_t)(b * HH + h1) * DD);
#pragma unroll
    for (int i = 0; i < 8; i++) { q0[i] = qk0[l + 32 * i]; q1[i] = qk1[l + 32 * i]; }
    float qb0 = g_qbk[b * HH + h0], qb1 = g_qbk[b * HH + h1];

    float4* ck4 = (float4*)comb_key;

    // stage batch 0 (load + write-through)
#pragma unroll
    for (int r = 0; r < BATCH; r++) {
        int s = s0 + r;
        if (s < S_TOT) {
            float4 v = row_src(past_key, key, b, s)[t];
            buf[r * 256 + t] = v;
            ck4[((size_t)b * S_TOT + s) * 256 + t] = v;
        }
    }
    __syncthreads();

    for (int bt = 0; bt < nbt; bt++) {
        int bi = bt & 1;
        if (bt + 1 < nbt) {
#pragma unroll
            for (int r = 0; r < BATCH; r++) {
                int s = s0 + (bt + 1) * BATCH + r;
                if (s < S_TOT) {
                    float4 v = row_src(past_key, key, b, s)[t];
                    buf[((bt + 1) & 1) * (BATCH * 256) + r * 256 + t] = v;
                    ck4[((size_t)b * S_TOT + s) * 256 + t] = v;
                }
            }
        }
#pragma unroll
        for (int r = 0; r < BATCH; r++) {
            int s = s0 + bt * BATCH + r;
            if (s >= S_TOT) break;
            const ulonglong2* rb = (const ulonglong2*)(buf + bi * (BATCH * 256) + r * 256);
            unsigned long long a0 = 0ull, a1 = 0ull;
#pragma unroll
            for (int i = 0; i < 8; i++) {
                ulonglong2 x = rb[l + 32 * i];
                ffma2(a0, x.x, q0[i].x); ffma2(a0, x.y, q0[i].y);
                ffma2(a1, x.x, q1[i].x); ffma2(a1, x.y, q1[i].y);
            }
            float f0 = hadd2(a0), f1 = hadd2(a1);
#pragma unroll
            for (int off = 16; off; off >>= 1) {
                f0 += __shfl_xor_sync(~0u, f0, off);
                f1 += __shfl_xor_sync(~0u, f1, off);
            }
            if (l == 0) g_attn[(size_t)(b * HH + h0) * SP + s] = f0 + qb0;
            if (l == 1) g_attn[(size_t)(b * HH + h1) * SP + s] = f1 + qb1;
        }
        __syncthreads();
    }
}

// ---------------------------------------------------------------------------
// K3: per-(b,h) softmax over 4097 scores, normalized in place.
__global__ void __launch_bounds__(256) k_softmax() {
    int bh = blockIdx.x;
    int t = threadIdx.x;
    float* sc = g_attn + (size_t)bh * SP;
    float vals[17];
    int cnt = 0;
    float m = -1e30f;
    for (int i = t; i < S_TOT; i += 256) { float x = sc[i]; vals[cnt++] = x; m = fmaxf(m, x); }
    __shared__ float red[256];
    red[t] = m; __syncthreads();
    for (int off = 128; off; off >>= 1) { if (t < off) red[t] = fmaxf(red[t], red[t + off]); __syncthreads(); }
    m = red[0]; __syncthreads();
    float sum = 0.f;
    for (int j = 0; j < cnt; j++) { vals[j] = expf(vals[j] - m); sum += vals[j]; }
    red[t] = sum; __syncthreads();
    for (int off = 128; off; off >>= 1) { if (t < off) red[t] += red[t + off]; __syncthreads(); }
    float inv = 1.f / red[0];
    cnt = 0;
    for (int i = t; i < S_TOT; i += 256) sc[i] = vals[cnt++] * inv;
}

// ---------------------------------------------------------------------------
// K4: streaming attn-weighted value sum + comb_value write-through.
// 4-deep row prefetch ring; attn pre-packed f32x2 in SMEM; FFMA2 inner loop.
__global__ void __launch_bounds__(256, 2) k_vsum(const float* __restrict__ past_value,
                                                 const float* __restrict__ value,
                                                 float* __restrict__ comb_value) {
    int chunk = blockIdx.x, b = blockIdx.y;
    int t = threadIdx.x;
    int s0 = chunk * CHUNK, nrows = min(CHUNK, S_TOT - s0);

    __shared__ unsigned long long attn2[HH * CHUNK];
    for (int i = t; i < HH * CHUNK; i += 256) {
        int h = i >> 7, sl = i & 127;
        float a = (sl < nrows) ? g_attn[(size_t)(b * HH + h) * SP + s0 + sl] : 0.f;
        unsigned int u = __float_as_uint(a);
        attn2[i] = ((unsigned long long)u << 32) | (unsigned long long)u;
    }
    __syncthreads();

    unsigned long long acc[HH][2];
#pragma unroll
    for (int h = 0; h < HH; h++) { acc[h][0] = 0ull; acc[h][1] = 0ull; }

    ulonglong2 v[4];
#pragma unroll
    for (int p = 0; p < 4; p++)
        v[p] = (p < nrows) ? ((const ulonglong2*)row_src(past_value, value, b, s0 + p))[t]
                           : make_ulonglong2(0ull, 0ull);

    for (int r = 0; r < nrows; r++) {
        ulonglong2 cur = v[r & 3];
        if (r + 4 < nrows)
            v[r & 3] = ((const ulonglong2*)row_src(past_value, value, b, s0 + r + 4))[t];
        ((ulonglong2*)comb_value)[((size_t)b * S_TOT + s0 + r) * 256 + t] = cur;
#pragma unroll
        for (int h = 0; h < HH; h++) {
            unsigned long long a = attn2[h * CHUNK + r];
            ffma2(acc[h][0], a, cur.x);
            ffma2(acc[h][1], a, cur.y);
        }
    }
    ulonglong2* part = (ulonglong2*)(g_partial + (size_t)(b * NCH + chunk) * HH * DD);
#pragma unroll
    for (int h = 0; h < HH; h++)
        part[(size_t)h * 256 + t] = make_ulonglong2(acc[h][0], acc[h][1]);
}

// ---------------------------------------------------------------------------
// K5: reduce chunk partials (inline) + ctx projection.
__global__ void __launch_bounds__(256) k_ctx(const float* __restrict__ w_in,
                                             const float* __restrict__ b_in) {
    int b = blockIdx.y;
    int obase = blockIdx.x * 128;  // covers heads h0, h0+1
    int t = threadIdx.x, w = t >> 5, l = t & 31;
    int h0 = obase >> 6;
    __shared__ float ws[2 * DD];
    for (int i = t; i < 512; i += 256) {
        float4 acc = make_float4(0.f, 0.f, 0.f, 0.f);
        for (int c = 0; c < NCH; c++) {
            float4 p = ((const float4*)g_partial)[(size_t)(b * NCH + c) * HH * 256 + h0 * 256 + i];
            acc.x += p.x; acc.y += p.y; acc.z += p.z; acc.w += p.w;
        }
        ((float4*)ws)[i] = acc;
    }
    __syncthreads();
    for (int k = 0; k < 16; k++) {
        int o = obase + w * 16 + k;
        const float4* wr = (const float4*)(w_in + (size_t)(2 * DD + o) * DD);
        const float4* xs = (const float4*)(ws + ((o >> 6) - h0) * DD);
        float a = 0.f;
#pragma unroll
        for (int i = 0; i < 8; i++) {
            float4 x = xs[l + 32 * i], y = wr[l + 32 * i];
            a += x.x * y.x + x.y * y.y + x.z * y.z + x.w * y.w;
        }
#pragma unroll
        for (int off = 16; off; off >>= 1) a += __shfl_xor_sync(~0u, a, off);
        if (l == 0) g_ctx[b * DD + o] = a + b_in[2 * DD + o];
    }
}

// K6: out[b,p] = w_out[p,:] . ctx[b,:] + b_out[p]
__global__ void __launch_bounds__(256) k_out(const float* __restrict__ w_out,
                                             const float* __restrict__ b_out,
                                             float* __restrict__ out) {
    int b = blockIdx.y;
    int obase = blockIdx.x * 128;
    int t = threadIdx.x, w = t >> 5, l = t & 31;
    __shared__ float cx[DD];
    ((float4*)cx)[t] = ((const float4*)(g_ctx + (size_t)b * DD))[t];
    __syncthreads();
    const float4* c4 = (const float4*)cx;
    for (int k = 0; k < 16; k++) {
        int o = obase + w * 16 + k;
        const float4* wr = (const float4*)(w_out + (size_t)o * DD);
        float a = 0.f;
#pragma unroll
        for (int i = 0; i < 8; i++) {
            float4 x = c4[l + 32 * i], y = wr[l + 32 * i];
            a += x.x * y.x + x.y * y.y + x.z * y.z + x.w * y.w;
        }
#pragma unroll
        for (int off = 16; off; off >>= 1) a += __shfl_xor_sync(~0u, a, off);
        if (l == 0) out[b * DD + o] = a + b_out[o];
    }
}

// ---------------------------------------------------------------------------
extern "C" void kernel_launch(void* const* d_in, const int* in_sizes, int n_in,
                              void* d_out, int out_size) {
    const float* query      = (const float*)d_in[0];
    const float* key        = (const float*)d_in[1];
    const float* value      = (const float*)d_in[2];
    const float* past_key   = (const float*)d_in[3];
    const float* past_value = (const float*)d_in[4];
    const float* w_in       = (const float*)d_in[5];
    const float* b_in       = (const float*)d_in[6];
    const float* w_out      = (const float*)d_in[7];
    const float* b_out      = (const float*)d_in[8];

    float* out        = (float*)d_out;
    float* comb_key   = out + (size_t)BB * DD;
    float* comb_value = comb_key + (size_t)BB * S_TOT * DD;

    const int scores_smem = 2 * BATCH * 256 * (int)sizeof(float4);  // 64 KB
    cudaFuncSetAttribute(k_scores, cudaFuncAttributeMaxDynamicSharedMemorySize, scores_smem);

    k_qproj  <<<dim3(8, BB), 256>>>(query, w_in, b_in);
    k_qkt    <<<dim3(HH, BB), 256>>>(w_in, b_in);
    k_scores <<<dim3(NCH, BB), 256, scores_smem>>>(past_key, key, comb_key);
    k_softmax<<<BB * HH, 256>>>();
    k_vsum   <<<dim3(NCH, BB), 256>>>(past_value, value, comb_value);
    k_ctx    <<<dim3(8, BB), 256>>>(w_in, b_in);
    k_out    <<<dim3(8, BB), 256>>>(w_out, b_out, out);
}

// round 6
// speedup vs baseline: 1.6976x; 1.5133x over previous
#include <cuda_runtime.h>
#include <math.h>

#define BB 16
#define S_PAST 4096
#define S_TOT 4097
#define DD 1024
#define HH 16
#define HDI 64
#define SP 4104      // padded per-(b,h) score stride (floats)
#define CHUNK 128
#define NCH 33       // ceil(4097/128)
#define RPB 4        // rows per pipeline batch (16 KB)
#define NST 6        // pipeline stages
#define LOOKAHEAD 3
#define ROW_BYTES (DD * 4)

// ---------------- scratch (static device globals; no allocation) ----------------
__device__ __align__(16) float g_q[BB * DD];
__device__ __align__(16) float g_qkt[BB * HH * DD];
__device__ float g_qbk[BB * HH];
__device__ __align__(16) float g_attn[BB * HH * SP];
__device__ __align__(16) float g_partial[(size_t)BB * NCH * HH * DD];
__device__ __align__(16) float g_ctx[BB * DD];

// ---------------- packed f32x2 helpers ----------------
__device__ __forceinline__ void ffma2(unsigned long long& d, unsigned long long a,
                                      unsigned long long b) {
    asm("fma.rn.f32x2 %0, %1, %2, %0;" : "+l"(d) : "l"(a), "l"(b));
}
union U64F2 { unsigned long long u; float2 f; };
__device__ __forceinline__ float hadd2(unsigned long long a) {
    U64F2 t; t.u = a; return t.f.x + t.f.y;
}
__device__ __forceinline__ unsigned long long dup2(float x) {
    unsigned long long r;
    asm("mov.b64 %0, {%1, %1};" : "=l"(r) : "r"(__float_as_uint(x)));
    return r;
}

// ---------------- TMA / mbarrier helpers ----------------
__device__ __forceinline__ unsigned smem_u32(const void* p) {
    unsigned a;
    asm("{ .reg .u64 t; cvta.to.shared.u64 t, %1; cvt.u32.u64 %0, t; }" : "=r"(a) : "l"(p));
    return a;
}
__device__ __forceinline__ void mbar_init(unsigned a, unsigned cnt) {
    asm volatile("mbarrier.init.shared.b64 [%0], %1;" :: "r"(a), "r"(cnt) : "memory");
}
__device__ __forceinline__ void mbar_expect_tx(unsigned a, unsigned bytes) {
    asm volatile("mbarrier.arrive.expect_tx.shared.b64 _, [%0], %1;" :: "r"(a), "r"(bytes) : "memory");
}
__device__ __forceinline__ void mbar_wait(unsigned a, unsigned ph) {
    asm volatile(
        "{\n\t.reg .pred P;\n"
        "W0_%=:\n\t"
        "mbarrier.try_wait.parity.acquire.cta.shared::cta.b64 P, [%0], %1, 0x989680;\n\t"
        "@P bra W1_%=;\n\t"
        "bra W0_%=;\n"
        "W1_%=:\n\t}"
        :: "r"(a), "r"(ph) : "memory");
}
__device__ __forceinline__ void bulk_g2s(unsigned dst, const void* src, unsigned bytes, unsigned mbar) {
    asm volatile("cp.async.bulk.shared::cluster.global.mbarrier::complete_tx::bytes [%0], [%1], %2, [%3];"
                 :: "r"(dst), "l"(src), "r"(bytes), "r"(mbar) : "memory");
}
__device__ __forceinline__ void bulk_s2g(void* dst, unsigned src, unsigned bytes) {
    asm volatile("cp.async.bulk.global.shared::cta.bulk_group [%0], [%1], %2;"
                 :: "l"(dst), "r"(src), "r"(bytes) : "memory");
}
__device__ __forceinline__ void bulk_commit() {
    asm volatile("cp.async.bulk.commit_group;" ::: "memory");
}
template <int N>
__device__ __forceinline__ void bulk_wait_read() {
    asm volatile("cp.async.bulk.wait_group.read %0;" :: "n"(N) : "memory");
}
__device__ __forceinline__ void bulk_wait_all() {
    asm volatile("cp.async.bulk.wait_group 0;" ::: "memory");
}

// ---------------------------------------------------------------------------
// K1a: q[b,o] = (query[b,:] . w_in[o,:] + b_in[o]) * hd^-0.5
__global__ void __launch_bounds__(256) k_qproj(const float* __restrict__ query,
                                               const float* __restrict__ w_in,
                                               const float* __restrict__ b_in) {
    int b = blockIdx.y;
    int obase = blockIdx.x * 128;
    int t = threadIdx.x, w = t >> 5, l = t & 31;
    __shared__ float q[DD];
    ((float4*)q)[t] = ((const float4*)(query + (size_t)b * DD))[t];
    __syncthreads();
    const float4* q4 = (const float4*)q;
    for (int k = 0; k < 16; k++) {
        int o = obase + w * 16 + k;
        const float4* wr = (const float4*)(w_in + (size_t)o * DD);
        float a = 0.f;
#pragma unroll
        for (int i = 0; i < 8; i++) {
            float4 x = q4[l + 32 * i], y = wr[l + 32 * i];
            a += x.x * y.x + x.y * y.y + x.z * y.z + x.w * y.w;
        }
#pragma unroll
        for (int off = 16; off; off >>= 1) a += __shfl_xor_sync(~0u, a, off);
        if (l == 0) g_q[b * DD + o] = (a + b_in[o]) * 0.125f;
    }
}

// ---------------------------------------------------------------------------
// K1b: qkt[b,h,d] = sum_j q[b,64h+j] * w_in[D+64h+j, d];  qbk[b,h] = q_h . bk_h
__global__ void __launch_bounds__(256) k_qkt(const float* __restrict__ w_in,
                                             const float* __restrict__ b_in) {
    int b = blockIdx.y, h = blockIdx.x;
    int t = threadIdx.x;
    __shared__ float qh[HDI];
    if (t < HDI) qh[t] = g_q[b * DD + h * HDI + t];
    __syncthreads();
    if (t == 0) {
        float s = 0.f;
        for (int j = 0; j < HDI; j++) s += qh[j] * b_in[DD + h * HDI + j];
        g_qbk[b * HH + h] = s;
    }
    float4 acc = make_float4(0.f, 0.f, 0.f, 0.f);
    const float4* wk4 = (const float4*)(w_in + (size_t)(DD + h * HDI) * DD);
#pragma unroll 4
    for (int j = 0; j < HDI; j++) {
        float qv = qh[j];
        float4 wv = wk4[(size_t)j * 256 + t];
        acc.x += qv * wv.x; acc.y += qv * wv.y; acc.z += qv * wv.z; acc.w += qv * wv.w;
    }
    ((float4*)g_qkt)[(size_t)(b * HH + h) * 256 + t] = acc;
}

// ---------------------------------------------------------------------------
// K2: TMA-pipelined scores + comb_key write-through.
// 6 stages x 4 rows (16KB). TMA bulk load in, compute from SMEM (2 heads/warp,
// qkt register-resident), TMA bulk-store copy out. No LDG/STG on the bulk data.
__global__ void __launch_bounds__(256, 2) k_scores(const float* __restrict__ past_key,
                                                   const float* __restrict__ key,
                                                   float* __restrict__ comb_key) {
    extern __shared__ __align__(128) float4 sbuf[];  // NST*RPB*256 float4 = 96KB
    __shared__ __align__(8) unsigned long long mbar_st[NST];
    int chunk = blockIdx.x, b = blockIdx.y;
    int t = threadIdx.x, w = t >> 5, l = t & 31;
    int s0 = chunk * CHUNK;
    int nrows = min(CHUNK, S_TOT - s0);
    int nbt = (nrows + RPB - 1) / RPB;

    unsigned sbase = smem_u32(sbuf);
    unsigned mb0 = smem_u32(&mbar_st[0]);

    const float* src_base = (chunk < 32) ? past_key + ((size_t)b * S_PAST + s0) * DD
                                         : key + (size_t)b * DD;
    float* dst_base = comb_key + ((size_t)b * S_TOT + s0) * DD;

    if (t == 0) {
        for (int i = 0; i < NST; i++) mbar_init(mb0 + 8 * i, 1);
    }
    __syncthreads();
    if (t == 0) {
        for (int i = 0; i < LOOKAHEAD && i < nbt; i++) {
            int rows = min(RPB, nrows - i * RPB);
            unsigned bytes = rows * ROW_BYTES;
            mbar_expect_tx(mb0 + 8 * i, bytes);
            bulk_g2s(sbase + i * (RPB * ROW_BYTES), src_base + (size_t)i * RPB * DD, bytes, mb0 + 8 * i);
        }
    }

    // per-warp head weights (register-resident, packed f32x2)
    int h0 = 2 * w, h1 = h0 + 1;
    ulonglong2 q0[8], q1[8];
    const ulonglong2* qk0 = (const ulonglong2*)(g_qkt + (size_t)(b * HH + h0) * DD);
    const ulonglong2* qk1 = (const ulonglong2*)(g_qkt + (size_t)(b * HH + h1) * DD);
#pragma unroll
    for (int i = 0; i < 8; i++) { q0[i] = qk0[l + 32 * i]; q1[i] = qk1[l + 32 * i]; }
    float qb0 = g_qbk[b * HH + h0], qb1 = g_qbk[b * HH + h1];

    for (int bt = 0; bt < nbt; bt++) {
        int st = bt % NST;
        unsigned ph = (bt / NST) & 1;
        int rows = min(RPB, nrows - bt * RPB);
        mbar_wait(mb0 + 8 * st, ph);

        if (t == 0) {  // copy-out this batch (pure SMEM read by TMA)
            bulk_s2g(dst_base + (size_t)bt * RPB * DD, sbase + st * (RPB * ROW_BYTES),
                     rows * ROW_BYTES);
            bulk_commit();
        }

        const ulonglong2* stg = (const ulonglong2*)(sbuf + st * (RPB * 256));
#pragma unroll
        for (int r = 0; r < RPB; r++) {
            if (r >= rows) break;
            const ulonglong2* rb = stg + r * 256;
            unsigned long long a0 = 0ull, a1 = 0ull;
#pragma unroll
            for (int i = 0; i < 8; i++) {
                ulonglong2 x = rb[l + 32 * i];
                ffma2(a0, x.x, q0[i].x); ffma2(a0, x.y, q0[i].y);
                ffma2(a1, x.x, q1[i].x); ffma2(a1, x.y, q1[i].y);
            }
            float f0 = hadd2(a0), f1 = hadd2(a1);
#pragma unroll
            for (int off = 16; off; off >>= 1) {
                f0 += __shfl_xor_sync(~0u, f0, off);
                f1 += __shfl_xor_sync(~0u, f1, off);
            }
            int s = s0 + bt * RPB + r;
            if (l == 0) g_attn[(size_t)(b * HH + h0) * SP + s] = f0 + qb0;
            if (l == 1) g_attn[(size_t)(b * HH + h1) * SP + s] = f1 + qb1;
        }
        __syncthreads();
        if (t == 0 && bt + LOOKAHEAD < nbt) {
            int nb = bt + LOOKAHEAD, nst = nb % NST;
            int nrw = min(RPB, nrows - nb * RPB);
            unsigned bytes = nrw * ROW_BYTES;
            bulk_wait_read<LOOKAHEAD>();   // stage (bt+3)%NST last stored at batch bt-3
            mbar_expect_tx(mb0 + 8 * nst, bytes);
            bulk_g2s(sbase + nst * (RPB * ROW_BYTES), src_base + (size_t)nb * RPB * DD, bytes, mb0 + 8 * nst);
        }
    }
    if (t == 0) bulk_wait_all();
}

// ---------------------------------------------------------------------------
// K3: per-(b,h) softmax over 4097 scores, vectorized float4.
__global__ void __launch_bounds__(256) k_softmax() {
    int bh = blockIdx.x;
    int t = threadIdx.x;
    float* sc = g_attn + (size_t)bh * SP;
    float4 v[4];
#pragma unroll
    for (int i = 0; i < 4; i++) v[i] = ((const float4*)sc)[t + 256 * i];
    float tail = sc[4096];
    float m = tail;
#pragma unroll
    for (int i = 0; i < 4; i++)
        m = fmaxf(m, fmaxf(fmaxf(v[i].x, v[i].y), fmaxf(v[i].z, v[i].w)));
    __shared__ float red[256];
    red[t] = m; __syncthreads();
    for (int off = 128; off; off >>= 1) { if (t < off) red[t] = fmaxf(red[t], red[t + off]); __syncthreads(); }
    m = red[0]; __syncthreads();
    float sum = 0.f;
#pragma unroll
    for (int i = 0; i < 4; i++) {
        v[i].x = expf(v[i].x - m); v[i].y = expf(v[i].y - m);
        v[i].z = expf(v[i].z - m); v[i].w = expf(v[i].w - m);
        sum += v[i].x + v[i].y + v[i].z + v[i].w;
    }
    float te = expf(tail - m);
    if (t == 0) sum += te;
    red[t] = sum; __syncthreads();
    for (int off = 128; off; off >>= 1) { if (t < off) red[t] += red[t + off]; __syncthreads(); }
    float inv = 1.f / red[0];
#pragma unroll
    for (int i = 0; i < 4; i++) {
        v[i].x *= inv; v[i].y *= inv; v[i].z *= inv; v[i].w *= inv;
        ((float4*)sc)[t + 256 * i] = v[i];
    }
    if (t == 0) sc[4096] = te * inv;
}

// ---------------------------------------------------------------------------
// K4: TMA-pipelined attn-weighted value sum + comb_value write-through.
// Same 6x4-row pipeline; compute reads SMEM only, copy-out is a bulk store.
__global__ void __launch_bounds__(256, 2) k_vsum(const float* __restrict__ past_value,
                                                 const float* __restrict__ value,
                                                 float* __restrict__ comb_value) {
    extern __shared__ __align__(128) float4 sbuf[];  // 96KB
    __shared__ __align__(8) unsigned long long mbar_st[NST];
    __shared__ float attn_s[HH * CHUNK];             // 8KB
    int chunk = blockIdx.x, b = blockIdx.y;
    int t = threadIdx.x;
    int s0 = chunk * CHUNK;
    int nrows = min(CHUNK, S_TOT - s0);
    int nbt = (nrows + RPB - 1) / RPB;

    unsigned sbase = smem_u32(sbuf);
    unsigned mb0 = smem_u32(&mbar_st[0]);

    const float* src_base = (chunk < 32) ? past_value + ((size_t)b * S_PAST + s0) * DD
                                         : value + (size_t)b * DD;
    float* dst_base = comb_value + ((size_t)b * S_TOT + s0) * DD;

    if (t == 0) {
        for (int i = 0; i < NST; i++) mbar_init(mb0 + 8 * i, 1);
    }
    __syncthreads();
    if (t == 0) {
        for (int i = 0; i < LOOKAHEAD && i < nbt; i++) {
            int rows = min(RPB, nrows - i * RPB);
            unsigned bytes = rows * ROW_BYTES;
            mbar_expect_tx(mb0 + 8 * i, bytes);
            bulk_g2s(sbase + i * (RPB * ROW_BYTES), src_base + (size_t)i * RPB * DD, bytes, mb0 + 8 * i);
        }
    }
    // stage attn weights for this (b, chunk)
    for (int i = t; i < HH * CHUNK; i += 256) {
        int h = i >> 7, sl = i & 127;
        attn_s[i] = (sl < nrows) ? g_attn[(size_t)(b * HH + h) * SP + s0 + sl] : 0.f;
    }
    __syncthreads();

    unsigned long long acc[HH][2];
#pragma unroll
    for (int h = 0; h < HH; h++) { acc[h][0] = 0ull; acc[h][1] = 0ull; }

    for (int bt = 0; bt < nbt; bt++) {
        int st = bt % NST;
        unsigned ph = (bt / NST) & 1;
        int rows = min(RPB, nrows - bt * RPB);
        mbar_wait(mb0 + 8 * st, ph);

        if (t == 0) {
            bulk_s2g(dst_base + (size_t)bt * RPB * DD, sbase + st * (RPB * ROW_BYTES),
                     rows * ROW_BYTES);
            bulk_commit();
        }

        const ulonglong2* stg = (const ulonglong2*)(sbuf + st * (RPB * 256));
#pragma unroll
        for (int r = 0; r < RPB; r++) {
            if (r >= rows) break;
            ulonglong2 cur = stg[r * 256 + t];
            const float* ar = attn_s + bt * RPB + r;
#pragma unroll
            for (int h = 0; h < HH; h++) {
                unsigned long long a2 = dup2(ar[h * CHUNK]);
                ffma2(acc[h][0], a2, cur.x);
                ffma2(acc[h][1], a2, cur.y);
            }
        }
        __syncthreads();
        if (t == 0 && bt + LOOKAHEAD < nbt) {
            int nb = bt + LOOKAHEAD, nst = nb % NST;
            int nrw = min(RPB, nrows - nb * RPB);
            unsigned bytes = nrw * ROW_BYTES;
            bulk_wait_read<LOOKAHEAD>();
            mbar_expect_tx(mb0 + 8 * nst, bytes);
            bulk_g2s(sbase + nst * (RPB * ROW_BYTES), src_base + (size_t)nb * RPB * DD, bytes, mb0 + 8 * nst);
        }
    }

    ulonglong2* part = (ulonglong2*)(g_partial + (size_t)(b * NCH + chunk) * HH * DD);
#pragma unroll
    for (int h = 0; h < HH; h++)
        part[(size_t)h * 256 + t] = make_ulonglong2(acc[h][0], acc[h][1]);
    if (t == 0) bulk_wait_all();
}

// ---------------------------------------------------------------------------
// K5: reduce chunk partials (inline) + ctx projection.
__global__ void __launch_bounds__(256) k_ctx(const float* __restrict__ w_in,
                                             const float* __restrict__ b_in) {
    int b = blockIdx.y;
    int obase = blockIdx.x * 128;  // covers heads h0, h0+1
    int t = threadIdx.x, w = t >> 5, l = t & 31;
    int h0 = obase >> 6;
    __shared__ float ws[2 * DD];
    for (int i = t; i < 512; i += 256) {
        float4 acc = make_float4(0.f, 0.f, 0.f, 0.f);
        for (int c = 0; c < NCH; c++) {
            float4 p = ((const float4*)g_partial)[(size_t)(b * NCH + c) * HH * 256 + h0 * 256 + i];
            acc.x += p.x; acc.y += p.y; acc.z += p.z; acc.w += p.w;
        }
        ((float4*)ws)[i] = acc;
    }
    __syncthreads();
    for (int k = 0; k < 16; k++) {
        int o = obase + w * 16 + k;
        const float4* wr = (const float4*)(w_in + (size_t)(2 * DD + o) * DD);
        const float4* xs = (const float4*)(ws + ((o >> 6) - h0) * DD);
        float a = 0.f;
#pragma unroll
        for (int i = 0; i < 8; i++) {
            float4 x = xs[l + 32 * i], y = wr[l + 32 * i];
            a += x.x * y.x + x.y * y.y + x.z * y.z + x.w * y.w;
        }
#pragma unroll
        for (int off = 16; off; off >>= 1) a += __shfl_xor_sync(~0u, a, off);
        if (l == 0) g_ctx[b * DD + o] = a + b_in[2 * DD + o];
    }
}

// K6: out[b,p] = w_out[p,:] . ctx[b,:] + b_out[p]
__global__ void __launch_bounds__(256) k_out(const float* __restrict__ w_out,
                                             const float* __restrict__ b_out,
                                             float* __restrict__ out) {
    int b = blockIdx.y;
    int obase = blockIdx.x * 128;
    int t = threadIdx.x, w = t >> 5, l = t & 31;
    __shared__ float cx[DD];
    ((float4*)cx)[t] = ((const float4*)(g_ctx + (size_t)b * DD))[t];
    __syncthreads();
    const float4* c4 = (const float4*)cx;
    for (int k = 0; k < 16; k++) {
        int o = obase + w * 16 + k;
        const float4* wr = (const float4*)(w_out + (size_t)o * DD);
        float a = 0.f;
#pragma unroll
        for (int i = 0; i < 8; i++) {
            float4 x = c4[l + 32 * i], y = wr[l + 32 * i];
            a += x.x * y.x + x.y * y.y + x.z * y.z + x.w * y.w;
        }
#pragma unroll
        for (int off = 16; off; off >>= 1) a += __shfl_xor_sync(~0u, a, off);
        if (l == 0) out[b * DD + o] = a + b_out[o];
    }
}

// ---------------------------------------------------------------------------
extern "C" void kernel_launch(void* const* d_in, const int* in_sizes, int n_in,
                              void* d_out, int out_size) {
    const float* query      = (const float*)d_in[0];
    const float* key        = (const float*)d_in[1];
    const float* value      = (const float*)d_in[2];
    const float* past_key   = (const float*)d_in[3];
    const float* past_value = (const float*)d_in[4];
    const float* w_in       = (const float*)d_in[5];
    const float* b_in       = (const float*)d_in[6];
    const float* w_out      = (const float*)d_in[7];
    const float* b_out      = (const float*)d_in[8];

    float* out        = (float*)d_out;
    float* comb_key   = out + (size_t)BB * DD;
    float* comb_value = comb_key + (size_t)BB * S_TOT * DD;

    const int pipe_smem = NST * RPB * ROW_BYTES;  // 96 KB
    cudaFuncSetAttribute(k_scores, cudaFuncAttributeMaxDynamicSharedMemorySize, pipe_smem);
    cudaFuncSetAttribute(k_vsum,   cudaFuncAttributeMaxDynamicSharedMemorySize, pipe_smem);

    k_qproj  <<<dim3(8, BB), 256>>>(query, w_in, b_in);
    k_qkt    <<<dim3(HH, BB), 256>>>(w_in, b_in);
    k_scores <<<dim3(NCH, BB), 256, pipe_smem>>>(past_key, key, comb_key);
    k_softmax<<<BB * HH, 256>>>();
    k_vsum   <<<dim3(NCH, BB), 256, pipe_smem>>>(past_value, value, comb_value);
    k_ctx    <<<dim3(8, BB), 256>>>(w_in, b_in);
    k_out    <<<dim3(8, BB), 256>>>(w_out, b_out, out);
}

// round 7
// speedup vs baseline: 1.9709x; 1.1610x over previous
#include <cuda_runtime.h>
#include <math.h>

#define BB 16
#define S_PAST 4096
#define S_TOT 4097
#define DD 1024
#define HH 16
#define HDI 64
#define CHUNK 108    // rows per chunk: 38*16 = 608 CTAs = exactly 2 waves on 152 SMs @ occ 2
#define NCH 38       // ceil(4097/108)
#define RPB 4        // rows per pipeline batch (16 KB)
#define NST 6        // pipeline stages
#define LOOKAHEAD 3
#define ROW_BYTES (DD * 4)
#define STAGE_BYTES (RPB * ROW_BYTES)

// ---------------- scratch (static device globals; no allocation) ----------------
__device__ __align__(16) float g_qkt[BB * HH * DD];
__device__ float g_qbk[BB * HH];
__device__ __align__(16) float2 g_ms[BB * NCH * HH];                 // per-(b,chunk,h) local (max, sum)
__device__ __align__(16) float g_partial[(size_t)BB * NCH * HH * DD]; // per-chunk weighted value sums
__device__ __align__(16) float g_ctx[BB * DD];

// ---------------- packed f32x2 helpers ----------------
__device__ __forceinline__ void ffma2(unsigned long long& d, unsigned long long a,
                                      unsigned long long b) {
    asm("fma.rn.f32x2 %0, %1, %2, %0;" : "+l"(d) : "l"(a), "l"(b));
}
union U64F2 { unsigned long long u; float2 f; };
__device__ __forceinline__ float hadd2(unsigned long long a) {
    U64F2 t; t.u = a; return t.f.x + t.f.y;
}
__device__ __forceinline__ unsigned long long dup2(float x) {
    unsigned long long r;
    asm("mov.b64 %0, {%1, %1};" : "=l"(r) : "r"(__float_as_uint(x)));
    return r;
}

// ---------------- TMA / mbarrier helpers ----------------
__device__ __forceinline__ unsigned smem_u32(const void* p) {
    unsigned a;
    asm("{ .reg .u64 t; cvta.to.shared.u64 t, %1; cvt.u32.u64 %0, t; }" : "=r"(a) : "l"(p));
    return a;
}
__device__ __forceinline__ void mbar_init(unsigned a, unsigned cnt) {
    asm volatile("mbarrier.init.shared.b64 [%0], %1;" :: "r"(a), "r"(cnt) : "memory");
}
__device__ __forceinline__ void mbar_expect_tx(unsigned a, unsigned bytes) {
    asm volatile("mbarrier.arrive.expect_tx.shared.b64 _, [%0], %1;" :: "r"(a), "r"(bytes) : "memory");
}
__device__ __forceinline__ void mbar_wait(unsigned a, unsigned ph) {
    asm volatile(
        "{\n\t.reg .pred P;\n"
        "W0_%=:\n\t"
        "mbarrier.try_wait.parity.acquire.cta.shared::cta.b64 P, [%0], %1, 0x989680;\n\t"
        "@P bra W1_%=;\n\t"
        "bra W0_%=;\n"
        "W1_%=:\n\t}"
        :: "r"(a), "r"(ph) : "memory");
}
__device__ __forceinline__ void bulk_g2s(unsigned dst, const float* src, unsigned bytes, unsigned mbar) {
    asm volatile("cp.async.bulk.shared::cluster.global.mbarrier::complete_tx::bytes [%0], [%1], %2, [%3];"
                 :: "r"(dst), "l"(src), "r"(bytes), "r"(mbar) : "memory");
}
__device__ __forceinline__ void bulk_s2g(float* dst, unsigned src, unsigned bytes) {
    asm volatile("cp.async.bulk.global.shared::cta.bulk_group [%0], [%1], %2;"
                 :: "l"(dst), "r"(src), "r"(bytes) : "memory");
}
__device__ __forceinline__ void bulk_commit() {
    asm volatile("cp.async.bulk.commit_group;" ::: "memory");
}
template <int N>
__device__ __forceinline__ void bulk_wait_read() {
    asm volatile("cp.async.bulk.wait_group.read %0;" :: "n"(N) : "memory");
}
__device__ __forceinline__ void bulk_wait_all() {
    asm volatile("cp.async.bulk.wait_group 0;" ::: "memory");
}

// ---------------------------------------------------------------------------
// K1: fused q projection + fold into per-head K weights.
// grid (HH, BB), block 256. Block (h,b): q_h[j] = (query[b]·w_in[h*64+j] + b)*0.125,
// then qkt[b,h,:] = sum_j q_h[j] * w_in[D+h*64+j,:],  qbk = q_h · bk_h.
__global__ void __launch_bounds__(256) k_qh(const float* __restrict__ query,
                                            const float* __restrict__ w_in,
                                            const float* __restrict__ b_in) {
    int b = blockIdx.y, h = blockIdx.x;
    int t = threadIdx.x, w = t >> 5, l = t & 31;
    __shared__ float qrow[DD];
    __shared__ float qh[HDI];
    ((float4*)qrow)[t] = ((const float4*)(query + (size_t)b * DD))[t];
    __syncthreads();
    const float4* q4 = (const float4*)qrow;
    for (int k = 0; k < 8; k++) {
        int ol = w * 8 + k;
        int o = h * HDI + ol;
        const float4* wr = (const float4*)(w_in + (size_t)o * DD);
        float a = 0.f;
#pragma unroll
        for (int i = 0; i < 8; i++) {
            float4 x = q4[l + 32 * i], y = wr[l + 32 * i];
            a += x.x * y.x + x.y * y.y + x.z * y.z + x.w * y.w;
        }
#pragma unroll
        for (int off = 16; off; off >>= 1) a += __shfl_xor_sync(~0u, a, off);
        if (l == 0) qh[ol] = (a + b_in[o]) * 0.125f;
    }
    __syncthreads();
    if (t == 0) {
        float s = 0.f;
        for (int j = 0; j < HDI; j++) s += qh[j] * b_in[DD + h * HDI + j];
        g_qbk[b * HH + h] = s;
    }
    float4 acc = make_float4(0.f, 0.f, 0.f, 0.f);
    const float4* wk4 = (const float4*)(w_in + (size_t)(DD + h * HDI) * DD);
#pragma unroll 4
    for (int j = 0; j < HDI; j++) {
        float qv = qh[j];
        float4 wv = wk4[(size_t)j * 256 + t];
        acc.x += qv * wv.x; acc.y += qv * wv.y; acc.z += qv * wv.z; acc.w += qv * wv.w;
    }
    ((float4*)g_qkt)[(size_t)(b * HH + h) * 256 + t] = acc;
}

// ---------------------------------------------------------------------------
// K2: fused streaming kernel. Per (b,chunk): TMA-pipeline K rows (scores into SMEM
// + comb_key write-through), local split-softmax, then TMA-pipeline V rows
// (exp-weighted partial sums + comb_value write-through). One continuous
// 2*nbt-batch pipeline; no DRAM round-trip for attention weights.
struct BInfo { const float* src; float* dst; int rows; };

__device__ __forceinline__ BInfo binfo(int j, int nbt1, int s0, int nrows, int b,
                                       const float* pk, const float* ky,
                                       const float* pv, const float* vl,
                                       float* ck, float* cv) {
    BInfo r;
    int isV = (j >= nbt1);
    int lb = isV ? j - nbt1 : j;
    int s_abs = s0 + lb * RPB;
    r.rows = min(RPB, nrows - lb * RPB);
    const float* past = isV ? pv : pk;
    const float* cur  = isV ? vl : ky;
    r.src = (s_abs < S_PAST) ? past + ((size_t)b * S_PAST + s_abs) * DD
                             : cur + (size_t)b * DD;
    r.dst = (isV ? cv : ck) + ((size_t)b * S_TOT + s_abs) * DD;
    return r;
}

__global__ void __launch_bounds__(256, 2) k_main(const float* __restrict__ past_key,
                                                 const float* __restrict__ key,
                                                 const float* __restrict__ past_value,
                                                 const float* __restrict__ value,
                                                 float* __restrict__ comb_key,
                                                 float* __restrict__ comb_value) {
    extern __shared__ __align__(128) float4 sbuf[];   // NST*STAGE_BYTES = 96KB
    __shared__ __align__(8) unsigned long long mbar_st[NST];
    __shared__ float sc[HH * CHUNK];                  // scores -> exp weights (6.75KB)
    int chunk = blockIdx.x, b = blockIdx.y;
    int t = threadIdx.x, w = t >> 5, l = t & 31;
    int s0 = chunk * CHUNK;
    int nrows = min(CHUNK, S_TOT - s0);
    int nbt1 = (nrows + RPB - 1) / RPB;
    int ntot = 2 * nbt1;

    unsigned sbase = smem_u32(sbuf);
    unsigned mb0 = smem_u32(&mbar_st[0]);

    if (t == 0) {
        for (int i = 0; i < NST; i++) mbar_init(mb0 + 8 * i, 1);
    }
    __syncthreads();
    if (t == 0) {
        for (int i = 0; i < LOOKAHEAD && i < ntot; i++) {
            BInfo bi = binfo(i, nbt1, s0, nrows, b, past_key, key, past_value, value,
                             comb_key, comb_value);
            unsigned bytes = bi.rows * ROW_BYTES;
            mbar_expect_tx(mb0 + 8 * i, bytes);
            bulk_g2s(sbase + i * STAGE_BYTES, bi.src, bytes, mb0 + 8 * i);
        }
    }

    // ---- K phase: scores ----
    {
        int h0 = 2 * w, h1 = h0 + 1;
        ulonglong2 q0[8], q1[8];
        const ulonglong2* qk0 = (const ulonglong2*)(g_qkt + (size_t)(b * HH + h0) * DD);
        const ulonglong2* qk1 = (const ulonglong2*)(g_qkt + (size_t)(b * HH + h1) * DD);
#pragma unroll
        for (int i = 0; i < 8; i++) { q0[i] = qk0[l + 32 * i]; q1[i] = qk1[l + 32 * i]; }
        float qb0 = g_qbk[b * HH + h0], qb1 = g_qbk[b * HH + h1];

        for (int bt = 0; bt < nbt1; bt++) {
            int st = bt % NST;
            unsigned ph = (bt / NST) & 1;
            BInfo bi = binfo(bt, nbt1, s0, nrows, b, past_key, key, past_value, value,
                             comb_key, comb_value);
            mbar_wait(mb0 + 8 * st, ph);
            if (t == 0) {
                bulk_s2g(bi.dst, sbase + st * STAGE_BYTES, bi.rows * ROW_BYTES);
                bulk_commit();
            }
            const ulonglong2* stg = (const ulonglong2*)(sbuf + st * (RPB * 256));
#pragma unroll
            for (int r = 0; r < RPB; r++) {
                if (r >= bi.rows) break;
                const ulonglong2* rb = stg + r * 256;
                unsigned long long a0a = 0ull, a0b = 0ull, a1a = 0ull, a1b = 0ull;
#pragma unroll
                for (int i = 0; i < 8; i++) {
                    ulonglong2 x = rb[l + 32 * i];
                    ffma2(a0a, x.x, q0[i].x); ffma2(a0b, x.y, q0[i].y);
                    ffma2(a1a, x.x, q1[i].x); ffma2(a1b, x.y, q1[i].y);
                }
                float f0 = hadd2(a0a) + hadd2(a0b);
                float f1 = hadd2(a1a) + hadd2(a1b);
#pragma unroll
                for (int off = 16; off; off >>= 1) {
                    f0 += __shfl_xor_sync(~0u, f0, off);
                    f1 += __shfl_xor_sync(~0u, f1, off);
                }
                int sl = bt * RPB + r;
                if (l == 0) sc[h0 * CHUNK + sl] = f0 + qb0;
                if (l == 1) sc[h1 * CHUNK + sl] = f1 + qb1;
            }
            __syncthreads();
            if (t == 0 && bt + LOOKAHEAD < ntot) {
                int nb = bt + LOOKAHEAD;
                BInfo nbi = binfo(nb, nbt1, s0, nrows, b, past_key, key, past_value, value,
                                  comb_key, comb_value);
                unsigned bytes = nbi.rows * ROW_BYTES;
                bulk_wait_read<LOOKAHEAD>();
                mbar_expect_tx(mb0 + 8 * (nb % NST), bytes);
                bulk_g2s(sbase + (nb % NST) * STAGE_BYTES, nbi.src, bytes, mb0 + 8 * (nb % NST));
            }
        }
    }

    // ---- local split-softmax: sc := exp(sc - m_c); record (m_c, s_c) ----
    {
#pragma unroll
        for (int hh = 2 * w; hh <= 2 * w + 1; hh++) {
            float* row = sc + hh * CHUNK;
            float m = -1e30f;
            for (int i = l; i < nrows; i += 32) m = fmaxf(m, row[i]);
#pragma unroll
            for (int off = 16; off; off >>= 1) m = fmaxf(m, __shfl_xor_sync(~0u, m, off));
            float s = 0.f;
            for (int i = l; i < nrows; i += 32) {
                float e = expf(row[i] - m);
                row[i] = e;
                s += e;
            }
#pragma unroll
            for (int off = 16; off; off >>= 1) s += __shfl_xor_sync(~0u, s, off);
            if (l == 0) g_ms[(size_t)(b * NCH + chunk) * HH + hh] = make_float2(m, s);
        }
        __syncthreads();
    }

    // ---- V phase: exp-weighted partial sums ----
    {
        unsigned long long acc[HH][2];
#pragma unroll
        for (int h = 0; h < HH; h++) { acc[h][0] = 0ull; acc[h][1] = 0ull; }

        for (int bt = nbt1; bt < ntot; bt++) {
            int st = bt % NST;
            unsigned ph = (bt / NST) & 1;
            int lb = bt - nbt1;
            BInfo bi = binfo(bt, nbt1, s0, nrows, b, past_key, key, past_value, value,
                             comb_key, comb_value);
            mbar_wait(mb0 + 8 * st, ph);
            if (t == 0) {
                bulk_s2g(bi.dst, sbase + st * STAGE_BYTES, bi.rows * ROW_BYTES);
                bulk_commit();
            }
            const ulonglong2* stg = (const ulonglong2*)(sbuf + st * (RPB * 256));
#pragma unroll
            for (int r = 0; r < RPB; r++) {
                if (r >= bi.rows) break;
                ulonglong2 cur = stg[r * 256 + t];
                const float* ar = sc + lb * RPB + r;
#pragma unroll
                for (int h = 0; h < HH; h++) {
                    unsigned long long a2 = dup2(ar[h * CHUNK]);
                    ffma2(acc[h][0], a2, cur.x);
                    ffma2(acc[h][1], a2, cur.y);
                }
            }
            __syncthreads();
            if (t == 0 && bt + LOOKAHEAD < ntot) {
                int nb = bt + LOOKAHEAD;
                BInfo nbi = binfo(nb, nbt1, s0, nrows, b, past_key, key, past_value, value,
                                  comb_key, comb_value);
                unsigned bytes = nbi.rows * ROW_BYTES;
                bulk_wait_read<LOOKAHEAD>();
                mbar_expect_tx(mb0 + 8 * (nb % NST), bytes);
                bulk_g2s(sbase + (nb % NST) * STAGE_BYTES, nbi.src, bytes, mb0 + 8 * (nb % NST));
            }
        }

        ulonglong2* part = (ulonglong2*)(g_partial + (size_t)(b * NCH + chunk) * HH * DD);
#pragma unroll
        for (int h = 0; h < HH; h++)
            part[(size_t)h * 256 + t] = make_ulonglong2(acc[h][0], acc[h][1]);
    }
    if (t == 0) bulk_wait_all();
}

// ---------------------------------------------------------------------------
// K3: split-softmax combine + partial reduce + ctx projection.
// grid (8, BB): block covers heads h0=2bx, h0+1.
__global__ void __launch_bounds__(256) k_ctx(const float* __restrict__ w_in,
                                             const float* __restrict__ b_in) {
    int b = blockIdx.y;
    int hx = blockIdx.x;          // head pair index
    int obase = hx * 128;
    int t = threadIdx.x, w = t >> 5, l = t & 31;
    __shared__ float scl[2][NCH];
    __shared__ float ws[2 * DD];

    if (t < 2) {
        int h = 2 * hx + t;
        float M = -1e30f;
        for (int c = 0; c < NCH; c++)
            M = fmaxf(M, g_ms[(size_t)(b * NCH + c) * HH + h].x);
        float S = 0.f;
        for (int c = 0; c < NCH; c++) {
            float2 ms = g_ms[(size_t)(b * NCH + c) * HH + h];
            S += expf(ms.x - M) * ms.y;
        }
        float invS = 1.f / S;
        for (int c = 0; c < NCH; c++) {
            float2 ms = g_ms[(size_t)(b * NCH + c) * HH + h];
            scl[t][c] = expf(ms.x - M) * invS;
        }
    }
    __syncthreads();

    for (int i = t; i < 512; i += 256) {
        int hs = i >> 8;           // 0 or 1
        int q = i & 255;
        float4 acc = make_float4(0.f, 0.f, 0.f, 0.f);
        for (int c = 0; c < NCH; c++) {
            float s = scl[hs][c];
            float4 p = ((const float4*)g_partial)[((size_t)(b * NCH + c) * HH + 2 * hx + hs) * 256 + q];
            acc.x += s * p.x; acc.y += s * p.y; acc.z += s * p.z; acc.w += s * p.w;
        }
        ((float4*)ws)[i] = acc;
    }
    __syncthreads();

    for (int k = 0; k < 16; k++) {
        int o = obase + w * 16 + k;
        const float4* wr = (const float4*)(w_in + (size_t)(2 * DD + o) * DD);
        const float4* xs = (const float4*)(ws + ((o >> 6) & 1) * DD);
        float a = 0.f;
#pragma unroll
        for (int i = 0; i < 8; i++) {
            float4 x = xs[l + 32 * i], y = wr[l + 32 * i];
            a += x.x * y.x + x.y * y.y + x.z * y.z + x.w * y.w;
        }
#pragma unroll
        for (int off = 16; off; off >>= 1) a += __shfl_xor_sync(~0u, a, off);
        if (l == 0) g_ctx[b * DD + o] = a + b_in[2 * DD + o];
    }
}

// K4: out[b,p] = w_out[p,:] . ctx[b,:] + b_out[p]
__global__ void __launch_bounds__(256) k_out(const float* __restrict__ w_out,
                                             const float* __restrict__ b_out,
                                             float* __restrict__ out) {
    int b = blockIdx.y;
    int obase = blockIdx.x * 128;
    int t = threadIdx.x, w = t >> 5, l = t & 31;
    __shared__ float cx[DD];
    ((float4*)cx)[t] = ((const float4*)(g_ctx + (size_t)b * DD))[t];
    __syncthreads();
    const float4* c4 = (const float4*)cx;
    for (int k = 0; k < 16; k++) {
        int o = obase + w * 16 + k;
        const float4* wr = (const float4*)(w_out + (size_t)o * DD);
        float a = 0.f;
#pragma unroll
        for (int i = 0; i < 8; i++) {
            float4 x = c4[l + 32 * i], y = wr[l + 32 * i];
            a += x.x * y.x + x.y * y.y + x.z * y.z + x.w * y.w;
        }
#pragma unroll
        for (int off = 16; off; off >>= 1) a += __shfl_xor_sync(~0u, a, off);
        if (l == 0) out[b * DD + o] = a + b_out[o];
    }
}

// ---------------------------------------------------------------------------
extern "C" void kernel_launch(void* const* d_in, const int* in_sizes, int n_in,
                              void* d_out, int out_size) {
    const float* query      = (const float*)d_in[0];
    const float* key        = (const float*)d_in[1];
    const float* value      = (const float*)d_in[2];
    const float* past_key   = (const float*)d_in[3];
    const float* past_value = (const float*)d_in[4];
    const float* w_in       = (const float*)d_in[5];
    const float* b_in       = (const float*)d_in[6];
    const float* w_out      = (const float*)d_in[7];
    const float* b_out      = (const float*)d_in[8];

    float* out        = (float*)d_out;
    float* comb_key   = out + (size_t)BB * DD;
    float* comb_value = comb_key + (size_t)BB * S_TOT * DD;

    const int pipe_smem = NST * STAGE_BYTES;  // 96 KB
    cudaFuncSetAttribute(k_main, cudaFuncAttributeMaxDynamicSharedMemorySize, pipe_smem);

    k_qh  <<<dim3(HH, BB), 256>>>(query, w_in, b_in);
    k_main<<<dim3(NCH, BB), 256, pipe_smem>>>(past_key, key, past_value, value,
                                              comb_key, comb_value);
    k_ctx <<<dim3(8, BB), 256>>>(w_in, b_in);
    k_out <<<dim3(8, BB), 256>>>(w_out, b_out, out);
}